// round 7
// baseline (speedup 1.0000x reference)
#include <cuda_runtime.h>
#include <stdint.h>

#define NTHREADS 256
#define DEPTH 2

// ---------------- PTX helpers ----------------
__device__ __forceinline__ uint32_t smem_u32(const void* p) {
    return (uint32_t)__cvta_generic_to_shared(p);
}
__device__ __forceinline__ void mbar_init(uint32_t a, uint32_t cnt) {
    asm volatile("mbarrier.init.shared.b64 [%0], %1;" :: "r"(a), "r"(cnt) : "memory");
}
__device__ __forceinline__ void mbar_expect_tx(uint32_t a, uint32_t bytes) {
    asm volatile("mbarrier.arrive.expect_tx.shared.b64 _, [%0], %1;" :: "r"(a), "r"(bytes) : "memory");
}
__device__ __forceinline__ void mbar_arrive(uint32_t a) {
    asm volatile("mbarrier.arrive.shared.b64 _, [%0];" :: "r"(a) : "memory");
}
__device__ __forceinline__ void mbar_wait(uint32_t a, uint32_t phase) {
    asm volatile(
        "{\n\t.reg .pred P;\n\t"
        "WAIT_%=:\n\t"
        "mbarrier.try_wait.parity.acquire.cta.shared::cta.b64 P, [%0], %1, 0x989680;\n\t"
        "@P bra.uni DONE_%=;\n\t"
        "bra.uni WAIT_%=;\n\t"
        "DONE_%=:\n\t}"
        :: "r"(a), "r"(phase) : "memory");
}
// 1D bulk async copy gmem -> smem, completion via mbarrier complete_tx.
__device__ __forceinline__ void bulk_g2s(uint32_t sdst, const void* gsrc,
                                         uint32_t bytes, uint32_t mbar) {
    asm volatile(
        "cp.async.bulk.shared::cluster.global.mbarrier::complete_tx::bytes [%0], [%1], %2, [%3];"
        :: "r"(sdst), "l"(gsrc), "r"(bytes), "r"(mbar) : "memory");
}

// ---------------- math helpers ----------------
__device__ __forceinline__ float silu_fast(float x) {
    return __fdividef(x, 1.0f + __expf(-x));   // MUFU.EX2 + MUFU.RCP
}
// round-half-even then clamp in float domain == clip(round(a/scale))
__device__ __forceinline__ float quantf(float a, float inv_scale) {
    return fminf(fmaxf(rintf(a * inv_scale), -127.0f), 127.0f);
}
__device__ __forceinline__ int quanti(float a, float inv_scale) {
    int q = __float2int_rn(a * inv_scale);
    return max(-127, min(127, q));
}

// Persistent CTA, bulk-copy double-buffered pipeline.
// Slot s (16KB = gate||up row) is refilled for token j+DEPTH as soon as all
// 256 threads have drained it at token j -> one full row fetch is in flight
// per CTA at all times, independent of compute/reduce/store phases.
template <int D4PER, bool OUT_FLOAT>
__global__ __launch_bounds__(NTHREADS, 6)
void swiglu_quant_tma(const float* __restrict__ input,
                      const float* __restrict__ smooth_scale,
                      const int*   __restrict__ sorted_ids,
                      const int*   __restrict__ topk,
                      void*        __restrict__ qout,
                      float*       __restrict__ qscale,
                      int d, int N)
{
    extern __shared__ __align__(128) unsigned char smem_raw[];
    const int rowBytes = 8 * d;                      // 2*d floats, contiguous gate||up
    float* bufs = reinterpret_cast<float*>(smem_raw);
    unsigned char* tail = smem_raw + (size_t)DEPTH * rowBytes;
    unsigned long long* mb = reinterpret_cast<unsigned long long*>(tail); // [full0,full1,empty0,empty1]
    float* wmax = reinterpret_cast<float*>(mb + 2 * DEPTH);               // [2][NTHREADS/32]

    const int t      = threadIdx.x;
    const int bid    = blockIdx.x;
    const int stride = gridDim.x;
    if (bid >= N) return;
    const int n_iter = (N - bid + stride - 1) / stride;

    uint32_t full_a[DEPTH], empty_a[DEPTH];
    #pragma unroll
    for (int s = 0; s < DEPTH; s++) {
        full_a[s]  = smem_u32(mb + s);
        empty_a[s] = smem_u32(mb + DEPTH + s);
    }
    const uint32_t buf_base = smem_u32(bufs);

    if (t == 0) {
        #pragma unroll
        for (int s = 0; s < DEPTH; s++) {
            mbar_init(full_a[s], 1);
            mbar_init(empty_a[s], NTHREADS);
        }
    }
    __syncthreads();

    // Prologue: fill both slots.
    if (t == 0) {
        #pragma unroll
        for (int j = 0; j < DEPTH; j++) {
            if (j < n_iter) {
                const int tok = bid + j * stride;
                const int sid = __ldg(sorted_ids + tok);
                mbar_expect_tx(full_a[j], (uint32_t)rowBytes);
                bulk_g2s(buf_base + (uint32_t)j * rowBytes,
                         input + (size_t)sid * (size_t)(2 * d),
                         (uint32_t)rowBytes, full_a[j]);
            }
        }
    }

    int fullPhase[DEPTH]  = {0, 0};
    int emptyPhase[DEPTH] = {0, 0};

    for (int j = 0; j < n_iter; j++) {
        const int s     = j & 1;
        const int token = bid + j * stride;
        const int e     = __ldg(topk + token);

        mbar_wait(full_a[s], (uint32_t)fullPhase[s]);
        fullPhase[s] ^= 1;

        const float4* gate = reinterpret_cast<const float4*>(bufs + (size_t)s * (size_t)(2 * d));
        const float4* up   = gate + (d >> 2);
        const float4* ss   = reinterpret_cast<const float4*>(smooth_scale + (size_t)e * (size_t)d);

        float4 act[D4PER];
        float amax = 0.0f;
        #pragma unroll
        for (int k = 0; k < D4PER; k++) {
            const int i = t + k * NTHREADS;
            const float4 g = gate[i];        // LDS.128, conflict-free
            const float4 u = up[i];
            const float4 sc = __ldg(ss + i); // 64KB table, L1-resident
            float4 a;
            a.x = silu_fast(g.x) * u.x * sc.x;
            a.y = silu_fast(g.y) * u.y * sc.y;
            a.z = silu_fast(g.z) * u.z * sc.z;
            a.w = silu_fast(g.w) * u.w * sc.w;
            act[k] = a;
            amax = fmaxf(amax, fmaxf(fmaxf(fabsf(a.x), fabsf(a.y)),
                                     fmaxf(fabsf(a.z), fabsf(a.w))));
        }

        // Slot drained by this thread -> signal empty.
        mbar_arrive(empty_a[s]);

        // Producer: refill slot s with token j+DEPTH as soon as the slot is free.
        if (t == 0 && j + DEPTH < n_iter) {
            mbar_wait(empty_a[s], (uint32_t)emptyPhase[s]);
            emptyPhase[s] ^= 1;
            const int tok2 = bid + (j + DEPTH) * stride;
            const int sid2 = __ldg(sorted_ids + tok2);
            mbar_expect_tx(full_a[s], (uint32_t)rowBytes);
            bulk_g2s(buf_base + (uint32_t)s * rowBytes,
                     input + (size_t)sid2 * (size_t)(2 * d),
                     (uint32_t)rowBytes, full_a[s]);
        }

        // Block amax (single barrier; wmax parity double-buffered by j&1).
        float am = amax;
        #pragma unroll
        for (int o = 16; o > 0; o >>= 1)
            am = fmaxf(am, __shfl_xor_sync(0xffffffffu, am, o));
        float* wm = wmax + (j & 1) * (NTHREADS / 32);
        if ((t & 31) == 0) wm[t >> 5] = am;
        __syncthreads();
        float bmax = wm[0];
        #pragma unroll
        for (int w = 1; w < NTHREADS / 32; w++) bmax = fmaxf(bmax, wm[w]);

        const float scale     = (bmax > 0.0f) ? __fdiv_rn(bmax, 127.0f) : 1.0f;
        const float inv_scale = (bmax > 0.0f) ? __fdividef(127.0f, bmax) : 1.0f;
        if (t == 0) qscale[token] = scale;

        if (OUT_FLOAT) {
            float4* orow = reinterpret_cast<float4*>((float*)qout + (size_t)token * (size_t)d);
            #pragma unroll
            for (int k = 0; k < D4PER; k++) {
                const int i = t + k * NTHREADS;
                const float4 a = act[k];
                float4 f;
                f.x = quantf(a.x, inv_scale);
                f.y = quantf(a.y, inv_scale);
                f.z = quantf(a.z, inv_scale);
                f.w = quantf(a.w, inv_scale);
                __stcs(orow + i, f);   // streaming store; output never re-read
            }
        } else {
            char4* orow = reinterpret_cast<char4*>((int8_t*)qout + (size_t)token * (size_t)d);
            #pragma unroll
            for (int k = 0; k < D4PER; k++) {
                const int i = t + k * NTHREADS;
                const float4 a = act[k];
                char4 c;
                c.x = (char)quanti(a.x, inv_scale);
                c.y = (char)quanti(a.y, inv_scale);
                c.z = (char)quanti(a.z, inv_scale);
                c.w = (char)quanti(a.w, inv_scale);
                orow[i] = c;
            }
        }
    }
}

// Generic fallback for any d (smem-staged act), one CTA per token.
template <bool OUT_FLOAT>
__global__ __launch_bounds__(NTHREADS, 1)
void swiglu_quant_generic(const float* __restrict__ input,
                          const float* __restrict__ smooth_scale,
                          const int*   __restrict__ sorted_ids,
                          const int*   __restrict__ topk,
                          void*        __restrict__ qout,
                          float*       __restrict__ qscale,
                          int d)
{
    extern __shared__ float s_act[];
    const int token = blockIdx.x;
    const int t     = threadIdx.x;

    const int sid = __ldg(sorted_ids + token);
    const int e   = __ldg(topk + token);

    const float* gate = input + (size_t)sid * (size_t)(2 * d);
    const float* up   = gate + d;
    const float* ss   = smooth_scale + (size_t)e * (size_t)d;

    float amax = 0.0f;
    for (int j = t; j < d; j += NTHREADS) {
        float a = silu_fast(__ldg(gate + j)) * __ldg(up + j) * __ldg(ss + j);
        s_act[j] = a;
        amax = fmaxf(amax, fabsf(a));
    }

    __shared__ float wmax[NTHREADS / 32];
    #pragma unroll
    for (int o = 16; o > 0; o >>= 1)
        amax = fmaxf(amax, __shfl_xor_sync(0xffffffffu, amax, o));
    if ((t & 31) == 0) wmax[t >> 5] = amax;
    __syncthreads();
    float bmax = wmax[0];
    #pragma unroll
    for (int w = 1; w < NTHREADS / 32; w++) bmax = fmaxf(bmax, wmax[w]);

    const float scale     = (bmax > 0.0f) ? __fdiv_rn(bmax, 127.0f) : 1.0f;
    const float inv_scale = (bmax > 0.0f) ? __fdividef(127.0f, bmax) : 1.0f;
    if (t == 0) qscale[token] = scale;

    if (OUT_FLOAT) {
        float* orow = (float*)qout + (size_t)token * (size_t)d;
        for (int j = t; j < d; j += NTHREADS)
            orow[j] = quantf(s_act[j], inv_scale);
    } else {
        int8_t* orow = (int8_t*)qout + (size_t)token * (size_t)d;
        for (int j = t; j < d; j += NTHREADS)
            orow[j] = (int8_t)quanti(s_act[j], inv_scale);
    }
}

extern "C" void kernel_launch(void* const* d_in, const int* in_sizes, int n_in,
                              void* d_out, int out_size)
{
    const float* input        = (const float*)d_in[0];
    const float* smooth_scale = (const float*)d_in[1];
    const int*   sorted_ids   = (const int*)d_in[2];
    const int*   topk         = (const int*)d_in[3];

    const int N   = in_sizes[2];             // tokens (16384)
    const int fc1 = in_sizes[0] / N;         // 4096
    const int d   = fc1 / 2;                 // 2048

    // Output packing (f32 common dtype confirmed in R3/R4):
    const long long want_f32 = (long long)N * d + N;
    const bool out_float = ((long long)out_size == want_f32);

    void*  qout   = d_out;
    float* qscale = out_float
        ? ((float*)d_out + (size_t)N * (size_t)d)
        : (float*)((int8_t*)d_out + (size_t)N * (size_t)d);

    int sms = 148;
    cudaDeviceGetAttribute(&sms, cudaDevAttrMultiProcessorCount, 0);
    int grid = sms * 6;
    if (grid > N) grid = N;

    const int rowBytes = 8 * d;                               // 16 KB for d=2048
    const int smemBytes = DEPTH * rowBytes + 256;             // buffers + barriers + wmax
    const int per = d / (4 * NTHREADS);
    const bool fast = (d % (4 * NTHREADS) == 0) && per >= 1 && per <= 4
                      && smemBytes <= 48 * 1024;

    if (fast) {
        if (out_float) {
            switch (per) {
                case 1: swiglu_quant_tma<1, true><<<grid, NTHREADS, smemBytes>>>(input, smooth_scale, sorted_ids, topk, qout, qscale, d, N); break;
                case 2: swiglu_quant_tma<2, true><<<grid, NTHREADS, smemBytes>>>(input, smooth_scale, sorted_ids, topk, qout, qscale, d, N); break;
                case 3: swiglu_quant_tma<3, true><<<grid, NTHREADS, smemBytes>>>(input, smooth_scale, sorted_ids, topk, qout, qscale, d, N); break;
                default: swiglu_quant_tma<4, true><<<grid, NTHREADS, smemBytes>>>(input, smooth_scale, sorted_ids, topk, qout, qscale, d, N); break;
            }
        } else {
            switch (per) {
                case 1: swiglu_quant_tma<1, false><<<grid, NTHREADS, smemBytes>>>(input, smooth_scale, sorted_ids, topk, qout, qscale, d, N); break;
                case 2: swiglu_quant_tma<2, false><<<grid, NTHREADS, smemBytes>>>(input, smooth_scale, sorted_ids, topk, qout, qscale, d, N); break;
                case 3: swiglu_quant_tma<3, false><<<grid, NTHREADS, smemBytes>>>(input, smooth_scale, sorted_ids, topk, qout, qscale, d, N); break;
                default: swiglu_quant_tma<4, false><<<grid, NTHREADS, smemBytes>>>(input, smooth_scale, sorted_ids, topk, qout, qscale, d, N); break;
            }
        }
    } else {
        if (out_float)
            swiglu_quant_generic<true><<<N, NTHREADS, d * sizeof(float)>>>(input, smooth_scale, sorted_ids, topk, qout, qscale, d);
        else
            swiglu_quant_generic<false><<<N, NTHREADS, d * sizeof(float)>>>(input, smooth_scale, sorted_ids, topk, qout, qscale, d);
    }
}

// round 8
// speedup vs baseline: 1.2187x; 1.2187x over previous
#include <cuda_runtime.h>
#include <stdint.h>

#define NTHREADS 128   // 4 warps per token; 10 CTAs/SM -> 10 independent row gathers per SM

__device__ __forceinline__ float silu_fast(float x) {
    return __fdividef(x, 1.0f + __expf(-x));   // MUFU.EX2 + MUFU.RCP
}

// Float-domain quantize: rint (half-to-even, == jnp.round) then clamp.
// +-127 are exact floats and rint is monotone -> equals clip(round(a/scale)).
__device__ __forceinline__ float quantf(float a, float inv_scale) {
    return fminf(fmaxf(rintf(a * inv_scale), -127.0f), 127.0f);
}
__device__ __forceinline__ int quanti(float a, float inv_scale) {
    int q = __float2int_rn(a * inv_scale);
    return max(-127, min(127, q));
}

// One CTA per token, 128 threads, d == 4*NTHREADS*D4PER, act in registers.
template <int D4PER, bool OUT_FLOAT>
__global__ __launch_bounds__(NTHREADS, 10)
void swiglu_quant_fast(const float* __restrict__ input,
                       const float* __restrict__ smooth_scale,
                       const int*   __restrict__ sorted_ids,
                       const int*   __restrict__ topk,
                       void*        __restrict__ qout,
                       float*       __restrict__ qscale,
                       int d)
{
    const int token = blockIdx.x;
    const int t     = threadIdx.x;

    const int sid = __ldg(sorted_ids + token);
    const int e   = __ldg(topk + token);

    const float4* gate = reinterpret_cast<const float4*>(input + (size_t)sid * (size_t)(2 * d));
    const float4* up   = gate + (d >> 2);
    const float4* ss   = reinterpret_cast<const float4*>(smooth_scale + (size_t)e * (size_t)d);

    float4 act[D4PER];
    float amax = 0.0f;

    #pragma unroll
    for (int k = 0; k < D4PER; k++) {
        const int i = t + k * NTHREADS;
        const float4 g = __ldg(gate + i);
        const float4 u = __ldg(up + i);
        const float4 s = __ldg(ss + i);   // 64KB table, L1/L2-resident
        float4 a;
        a.x = silu_fast(g.x) * u.x * s.x;
        a.y = silu_fast(g.y) * u.y * s.y;
        a.z = silu_fast(g.z) * u.z * s.z;
        a.w = silu_fast(g.w) * u.w * s.w;
        act[k] = a;
        amax = fmaxf(amax, fmaxf(fmaxf(fabsf(a.x), fabsf(a.y)),
                                 fmaxf(fabsf(a.z), fabsf(a.w))));
    }

    // Block amax over 4 warps: shuffle reduce, 4-entry smem, one cheap barrier.
    __shared__ float wmax[NTHREADS / 32];
    #pragma unroll
    for (int o = 16; o > 0; o >>= 1)
        amax = fmaxf(amax, __shfl_xor_sync(0xffffffffu, amax, o));
    if ((t & 31) == 0) wmax[t >> 5] = amax;
    __syncthreads();
    float bmax = wmax[0];
    #pragma unroll
    for (int w = 1; w < NTHREADS / 32; w++) bmax = fmaxf(bmax, wmax[w]);

    // Emitted scale matches the reference exactly (IEEE divide); quantize by
    // the hoisted fast reciprocal-scale.
    const float scale     = (bmax > 0.0f) ? __fdiv_rn(bmax, 127.0f) : 1.0f;
    const float inv_scale = (bmax > 0.0f) ? __fdividef(127.0f, bmax) : 1.0f;
    if (t == 0) qscale[token] = scale;

    if (OUT_FLOAT) {
        float4* orow = reinterpret_cast<float4*>((float*)qout + (size_t)token * (size_t)d);
        #pragma unroll
        for (int k = 0; k < D4PER; k++) {
            const int i = t + k * NTHREADS;
            const float4 a = act[k];
            float4 f;
            f.x = quantf(a.x, inv_scale);
            f.y = quantf(a.y, inv_scale);
            f.z = quantf(a.z, inv_scale);
            f.w = quantf(a.w, inv_scale);
            __stcs(orow + i, f);   // streaming store: output never re-read
        }
    } else {
        char4* orow = reinterpret_cast<char4*>((int8_t*)qout + (size_t)token * (size_t)d);
        #pragma unroll
        for (int k = 0; k < D4PER; k++) {
            const int i = t + k * NTHREADS;
            const float4 a = act[k];
            char4 c;
            c.x = (char)quanti(a.x, inv_scale);
            c.y = (char)quanti(a.y, inv_scale);
            c.z = (char)quanti(a.z, inv_scale);
            c.w = (char)quanti(a.w, inv_scale);
            orow[i] = c;
        }
    }
}

// Generic fallback for any d (smem-staged act), one CTA per token.
template <bool OUT_FLOAT>
__global__ __launch_bounds__(256, 1)
void swiglu_quant_generic(const float* __restrict__ input,
                          const float* __restrict__ smooth_scale,
                          const int*   __restrict__ sorted_ids,
                          const int*   __restrict__ topk,
                          void*        __restrict__ qout,
                          float*       __restrict__ qscale,
                          int d)
{
    extern __shared__ float s_act[];
    const int token = blockIdx.x;
    const int t     = threadIdx.x;

    const int sid = __ldg(sorted_ids + token);
    const int e   = __ldg(topk + token);

    const float* gate = input + (size_t)sid * (size_t)(2 * d);
    const float* up   = gate + d;
    const float* ss   = smooth_scale + (size_t)e * (size_t)d;

    float amax = 0.0f;
    for (int j = t; j < d; j += blockDim.x) {
        float a = silu_fast(__ldg(gate + j)) * __ldg(up + j) * __ldg(ss + j);
        s_act[j] = a;
        amax = fmaxf(amax, fabsf(a));
    }

    __shared__ float wmax[8];
    #pragma unroll
    for (int o = 16; o > 0; o >>= 1)
        amax = fmaxf(amax, __shfl_xor_sync(0xffffffffu, amax, o));
    if ((t & 31) == 0) wmax[t >> 5] = amax;
    __syncthreads();
    float bmax = wmax[0];
    #pragma unroll
    for (int w = 1; w < 8; w++) bmax = fmaxf(bmax, wmax[w]);

    const float scale     = (bmax > 0.0f) ? __fdiv_rn(bmax, 127.0f) : 1.0f;
    const float inv_scale = (bmax > 0.0f) ? __fdividef(127.0f, bmax) : 1.0f;
    if (t == 0) qscale[token] = scale;

    if (OUT_FLOAT) {
        float* orow = (float*)qout + (size_t)token * (size_t)d;
        for (int j = t; j < d; j += blockDim.x)
            orow[j] = quantf(s_act[j], inv_scale);
    } else {
        int8_t* orow = (int8_t*)qout + (size_t)token * (size_t)d;
        for (int j = t; j < d; j += blockDim.x)
            orow[j] = (int8_t)quanti(s_act[j], inv_scale);
    }
}

extern "C" void kernel_launch(void* const* d_in, const int* in_sizes, int n_in,
                              void* d_out, int out_size)
{
    const float* input        = (const float*)d_in[0];
    const float* smooth_scale = (const float*)d_in[1];
    const int*   sorted_ids   = (const int*)d_in[2];
    const int*   topk         = (const int*)d_in[3];

    const int N   = in_sizes[2];             // tokens (16384)
    const int fc1 = in_sizes[0] / N;         // 4096
    const int d   = fc1 / 2;                 // 2048

    // Output packing (f32 common dtype confirmed in R3/R4):
    const long long want_f32 = (long long)N * d + N;
    const bool out_float = ((long long)out_size == want_f32);

    void*  qout   = d_out;
    float* qscale = out_float
        ? ((float*)d_out + (size_t)N * (size_t)d)
        : (float*)((int8_t*)d_out + (size_t)N * (size_t)d);

    const int per = d / (4 * NTHREADS);      // float4s per thread per half (4 for d=2048)
    const bool fast = (d % (4 * NTHREADS) == 0) && per >= 1 && per <= 4;

    if (fast) {
        if (out_float) {
            switch (per) {
                case 1: swiglu_quant_fast<1, true><<<N, NTHREADS>>>(input, smooth_scale, sorted_ids, topk, qout, qscale, d); break;
                case 2: swiglu_quant_fast<2, true><<<N, NTHREADS>>>(input, smooth_scale, sorted_ids, topk, qout, qscale, d); break;
                case 3: swiglu_quant_fast<3, true><<<N, NTHREADS>>>(input, smooth_scale, sorted_ids, topk, qout, qscale, d); break;
                default: swiglu_quant_fast<4, true><<<N, NTHREADS>>>(input, smooth_scale, sorted_ids, topk, qout, qscale, d); break;
            }
        } else {
            switch (per) {
                case 1: swiglu_quant_fast<1, false><<<N, NTHREADS>>>(input, smooth_scale, sorted_ids, topk, qout, qscale, d); break;
                case 2: swiglu_quant_fast<2, false><<<N, NTHREADS>>>(input, smooth_scale, sorted_ids, topk, qout, qscale, d); break;
                case 3: swiglu_quant_fast<3, false><<<N, NTHREADS>>>(input, smooth_scale, sorted_ids, topk, qout, qscale, d); break;
                default: swiglu_quant_fast<4, false><<<N, NTHREADS>>>(input, smooth_scale, sorted_ids, topk, qout, qscale, d); break;
            }
        }
    } else {
        if (out_float)
            swiglu_quant_generic<true><<<N, 256, d * sizeof(float)>>>(input, smooth_scale, sorted_ids, topk, qout, qscale, d);
        else
            swiglu_quant_generic<false><<<N, 256, d * sizeof(float)>>>(input, smooth_scale, sorted_ids, topk, qout, qscale, d);
    }
}

// round 9
// speedup vs baseline: 1.3248x; 1.0871x over previous
#include <cuda_runtime.h>
#include <stdint.h>

#define NTHREADS 256

__device__ __forceinline__ float silu_fast(float x) {
    return __fdividef(x, 1.0f + __expf(-x));   // MUFU.EX2 + MUFU.RCP
}
// rint (half-to-even == jnp.round) then clamp in float domain.
__device__ __forceinline__ float quantf(float a, float inv_scale) {
    return fminf(fmaxf(rintf(a * inv_scale), -127.0f), 127.0f);
}
__device__ __forceinline__ int quanti(float a, float inv_scale) {
    int q = __float2int_rn(a * inv_scale);
    return max(-127, min(127, q));
}

__device__ __forceinline__ float amax4(float cur, float4 a) {
    return fmaxf(cur, fmaxf(fmaxf(fabsf(a.x), fabsf(a.y)),
                            fmaxf(fabsf(a.z), fabsf(a.w))));
}

// Two tokens per CTA, software-pipelined: token1's global loads are issued
// before token0's reduce/store phase (ptxas keeps LDGs before BAR.SYNC), so
// the DRAM pipe stays fed through the otherwise load-free tail of token0.
template <int D4PER, bool OUT_FLOAT>
__global__ __launch_bounds__(NTHREADS, 5)
void swiglu_quant_pair(const float* __restrict__ input,
                       const float* __restrict__ smooth_scale,
                       const int*   __restrict__ sorted_ids,
                       const int*   __restrict__ topk,
                       void*        __restrict__ qout,
                       float*       __restrict__ qscale,
                       int d, int N)
{
    const int t    = threadIdx.x;
    const int tok0 = blockIdx.x * 2;
    const int tok1 = tok0 + 1;
    const bool has1 = (tok1 < N);

    const int sid0 = __ldg(sorted_ids + tok0);
    const int e0   = __ldg(topk + tok0);
    int sid1 = sid0, e1 = e0;
    if (has1) { sid1 = __ldg(sorted_ids + tok1); e1 = __ldg(topk + tok1); }

    __shared__ float wmax[2][NTHREADS / 32];

    // ---- token0 loads (front-batched) ----
    const float4* g0 = reinterpret_cast<const float4*>(input + (size_t)sid0 * (size_t)(2 * d));
    const float4* u0 = g0 + (d >> 2);
    const float4* s0 = reinterpret_cast<const float4*>(smooth_scale + (size_t)e0 * (size_t)d);

    float4 A0[D4PER];
    {
        float4 G[D4PER], U[D4PER], S[D4PER];
        #pragma unroll
        for (int k = 0; k < D4PER; k++) {
            const int i = t + k * NTHREADS;
            G[k] = __ldg(g0 + i);
            U[k] = __ldg(u0 + i);
            S[k] = __ldg(s0 + i);
        }
        #pragma unroll
        for (int k = 0; k < D4PER; k++) {
            A0[k].x = silu_fast(G[k].x) * U[k].x * S[k].x;
            A0[k].y = silu_fast(G[k].y) * U[k].y * S[k].y;
            A0[k].z = silu_fast(G[k].z) * U[k].z * S[k].z;
            A0[k].w = silu_fast(G[k].w) * U[k].w * S[k].w;
        }
    }
    float am0 = 0.0f;
    #pragma unroll
    for (int k = 0; k < D4PER; k++) am0 = amax4(am0, A0[k]);

    // ---- token1 loads issued NOW (in flight during token0 reduce/store) ----
    const float4* g1 = reinterpret_cast<const float4*>(input + (size_t)sid1 * (size_t)(2 * d));
    const float4* u1 = g1 + (d >> 2);
    const float4* s1 = reinterpret_cast<const float4*>(smooth_scale + (size_t)e1 * (size_t)d);
    float4 G1[D4PER], U1[D4PER], S1[D4PER];
    if (has1) {
        #pragma unroll
        for (int k = 0; k < D4PER; k++) {
            const int i = t + k * NTHREADS;
            G1[k] = __ldg(g1 + i);
            U1[k] = __ldg(u1 + i);
            S1[k] = __ldg(s1 + i);
        }
    }

    // ---- token0 reduce + store ----
    {
        float am = am0;
        #pragma unroll
        for (int o = 16; o > 0; o >>= 1)
            am = fmaxf(am, __shfl_xor_sync(0xffffffffu, am, o));
        if ((t & 31) == 0) wmax[0][t >> 5] = am;
    }
    __syncthreads();
    {
        float bmax = wmax[0][0];
        #pragma unroll
        for (int w = 1; w < NTHREADS / 32; w++) bmax = fmaxf(bmax, wmax[0][w]);
        const float scale     = (bmax > 0.0f) ? __fdiv_rn(bmax, 127.0f) : 1.0f;
        const float inv_scale = (bmax > 0.0f) ? __fdividef(127.0f, bmax) : 1.0f;
        if (t == 0) qscale[tok0] = scale;

        if (OUT_FLOAT) {
            float4* orow = reinterpret_cast<float4*>((float*)qout + (size_t)tok0 * (size_t)d);
            #pragma unroll
            for (int k = 0; k < D4PER; k++) {
                const int i = t + k * NTHREADS;
                float4 f;
                f.x = quantf(A0[k].x, inv_scale);
                f.y = quantf(A0[k].y, inv_scale);
                f.z = quantf(A0[k].z, inv_scale);
                f.w = quantf(A0[k].w, inv_scale);
                __stcs(orow + i, f);
            }
        } else {
            char4* orow = reinterpret_cast<char4*>((int8_t*)qout + (size_t)tok0 * (size_t)d);
            #pragma unroll
            for (int k = 0; k < D4PER; k++) {
                const int i = t + k * NTHREADS;
                char4 c;
                c.x = (char)quanti(A0[k].x, inv_scale);
                c.y = (char)quanti(A0[k].y, inv_scale);
                c.z = (char)quanti(A0[k].z, inv_scale);
                c.w = (char)quanti(A0[k].w, inv_scale);
                orow[i] = c;
            }
        }
    }

    if (!has1) return;

    // ---- token1 compute (loads have had the whole token0 tail to land) ----
    float4 A1[D4PER];
    #pragma unroll
    for (int k = 0; k < D4PER; k++) {
        A1[k].x = silu_fast(G1[k].x) * U1[k].x * S1[k].x;
        A1[k].y = silu_fast(G1[k].y) * U1[k].y * S1[k].y;
        A1[k].z = silu_fast(G1[k].z) * U1[k].z * S1[k].z;
        A1[k].w = silu_fast(G1[k].w) * U1[k].w * S1[k].w;
    }
    float am1 = 0.0f;
    #pragma unroll
    for (int k = 0; k < D4PER; k++) am1 = amax4(am1, A1[k]);

    {
        float am = am1;
        #pragma unroll
        for (int o = 16; o > 0; o >>= 1)
            am = fmaxf(am, __shfl_xor_sync(0xffffffffu, am, o));
        if ((t & 31) == 0) wmax[1][t >> 5] = am;
    }
    __syncthreads();
    {
        float bmax = wmax[1][0];
        #pragma unroll
        for (int w = 1; w < NTHREADS / 32; w++) bmax = fmaxf(bmax, wmax[1][w]);
        const float scale     = (bmax > 0.0f) ? __fdiv_rn(bmax, 127.0f) : 1.0f;
        const float inv_scale = (bmax > 0.0f) ? __fdividef(127.0f, bmax) : 1.0f;
        if (t == 0) qscale[tok1] = scale;

        if (OUT_FLOAT) {
            float4* orow = reinterpret_cast<float4*>((float*)qout + (size_t)tok1 * (size_t)d);
            #pragma unroll
            for (int k = 0; k < D4PER; k++) {
                const int i = t + k * NTHREADS;
                float4 f;
                f.x = quantf(A1[k].x, inv_scale);
                f.y = quantf(A1[k].y, inv_scale);
                f.z = quantf(A1[k].z, inv_scale);
                f.w = quantf(A1[k].w, inv_scale);
                __stcs(orow + i, f);
            }
        } else {
            char4* orow = reinterpret_cast<char4*>((int8_t*)qout + (size_t)tok1 * (size_t)d);
            #pragma unroll
            for (int k = 0; k < D4PER; k++) {
                const int i = t + k * NTHREADS;
                char4 c;
                c.x = (char)quanti(A1[k].x, inv_scale);
                c.y = (char)quanti(A1[k].y, inv_scale);
                c.z = (char)quanti(A1[k].z, inv_scale);
                c.w = (char)quanti(A1[k].w, inv_scale);
                orow[i] = c;
            }
        }
    }
}

// Generic fallback for any d (smem-staged act), one CTA per token.
template <bool OUT_FLOAT>
__global__ __launch_bounds__(256, 1)
void swiglu_quant_generic(const float* __restrict__ input,
                          const float* __restrict__ smooth_scale,
                          const int*   __restrict__ sorted_ids,
                          const int*   __restrict__ topk,
                          void*        __restrict__ qout,
                          float*       __restrict__ qscale,
                          int d)
{
    extern __shared__ float s_act[];
    const int token = blockIdx.x;
    const int t     = threadIdx.x;

    const int sid = __ldg(sorted_ids + token);
    const int e   = __ldg(topk + token);

    const float* gate = input + (size_t)sid * (size_t)(2 * d);
    const float* up   = gate + d;
    const float* ss   = smooth_scale + (size_t)e * (size_t)d;

    float amax = 0.0f;
    for (int j = t; j < d; j += blockDim.x) {
        float a = silu_fast(__ldg(gate + j)) * __ldg(up + j) * __ldg(ss + j);
        s_act[j] = a;
        amax = fmaxf(amax, fabsf(a));
    }

    __shared__ float wmax[8];
    #pragma unroll
    for (int o = 16; o > 0; o >>= 1)
        amax = fmaxf(amax, __shfl_xor_sync(0xffffffffu, amax, o));
    if ((t & 31) == 0) wmax[t >> 5] = amax;
    __syncthreads();
    float bmax = wmax[0];
    #pragma unroll
    for (int w = 1; w < 8; w++) bmax = fmaxf(bmax, wmax[w]);

    const float scale     = (bmax > 0.0f) ? __fdiv_rn(bmax, 127.0f) : 1.0f;
    const float inv_scale = (bmax > 0.0f) ? __fdividef(127.0f, bmax) : 1.0f;
    if (t == 0) qscale[token] = scale;

    if (OUT_FLOAT) {
        float* orow = (float*)qout + (size_t)token * (size_t)d;
        for (int j = t; j < d; j += blockDim.x)
            orow[j] = quantf(s_act[j], inv_scale);
    } else {
        int8_t* orow = (int8_t*)qout + (size_t)token * (size_t)d;
        for (int j = t; j < d; j += blockDim.x)
            orow[j] = (int8_t)quanti(s_act[j], inv_scale);
    }
}

extern "C" void kernel_launch(void* const* d_in, const int* in_sizes, int n_in,
                              void* d_out, int out_size)
{
    const float* input        = (const float*)d_in[0];
    const float* smooth_scale = (const float*)d_in[1];
    const int*   sorted_ids   = (const int*)d_in[2];
    const int*   topk         = (const int*)d_in[3];

    const int N   = in_sizes[2];             // tokens (16384)
    const int fc1 = in_sizes[0] / N;         // 4096
    const int d   = fc1 / 2;                 // 2048

    // Output packing (f32 common dtype confirmed in R3/R4):
    const long long want_f32 = (long long)N * d + N;
    const bool out_float = ((long long)out_size == want_f32);

    void*  qout   = d_out;
    float* qscale = out_float
        ? ((float*)d_out + (size_t)N * (size_t)d)
        : (float*)((int8_t*)d_out + (size_t)N * (size_t)d);

    const int per = d / (4 * NTHREADS);      // float4s per thread per half (2 for d=2048)
    const bool fast = (d % (4 * NTHREADS) == 0) && per >= 1 && per <= 2;
    const int gridPair = (N + 1) / 2;

    if (fast) {
        if (out_float) {
            if (per == 1) swiglu_quant_pair<1, true><<<gridPair, NTHREADS>>>(input, smooth_scale, sorted_ids, topk, qout, qscale, d, N);
            else          swiglu_quant_pair<2, true><<<gridPair, NTHREADS>>>(input, smooth_scale, sorted_ids, topk, qout, qscale, d, N);
        } else {
            if (per == 1) swiglu_quant_pair<1, false><<<gridPair, NTHREADS>>>(input, smooth_scale, sorted_ids, topk, qout, qscale, d, N);
            else          swiglu_quant_pair<2, false><<<gridPair, NTHREADS>>>(input, smooth_scale, sorted_ids, topk, qout, qscale, d, N);
        }
    } else {
        if (out_float)
            swiglu_quant_generic<true><<<N, 256, d * sizeof(float)>>>(input, smooth_scale, sorted_ids, topk, qout, qscale, d);
        else
            swiglu_quant_generic<false><<<N, 256, d * sizeof(float)>>>(input, smooth_scale, sorted_ids, topk, qout, qscale, d);
    }
}

// round 10
// speedup vs baseline: 1.3409x; 1.0121x over previous
#include <cuda_runtime.h>
#include <stdint.h>

#define NTHREADS 256

__device__ __forceinline__ float silu_fast(float x) {
    return __fdividef(x, 1.0f + __expf(-x));   // MUFU.EX2 + MUFU.RCP
}
// rint (half-to-even == jnp.round) then clamp in float domain.
__device__ __forceinline__ float quantf(float a, float inv_scale) {
    return fminf(fmaxf(rintf(a * inv_scale), -127.0f), 127.0f);
}
__device__ __forceinline__ int quanti(float a, float inv_scale) {
    int q = __float2int_rn(a * inv_scale);
    return max(-127, min(127, q));
}
__device__ __forceinline__ float amax4(float cur, float4 a) {
    return fmaxf(cur, fmaxf(fmaxf(fabsf(a.x), fabsf(a.y)),
                            fmaxf(fabsf(a.z), fabsf(a.w))));
}

// Two tokens per CTA, software-pipelined. Token1's DRAM loads (gate/up only —
// smooth_scale is L1-resident and deferred) are issued before token0's
// reduce/store phase, so DRAM stays fed through the tail. Holding only G1/U1
// (16 regs) across the barrier keeps regs <= ~42 -> 6 CTAs/SM.
template <int D4PER, bool OUT_FLOAT>
__global__ __launch_bounds__(NTHREADS, 6)
void swiglu_quant_pair(const float* __restrict__ input,
                       const float* __restrict__ smooth_scale,
                       const int*   __restrict__ sorted_ids,
                       const int*   __restrict__ topk,
                       void*        __restrict__ qout,
                       float*       __restrict__ qscale,
                       int d, int N)
{
    const int t    = threadIdx.x;
    const int tok0 = blockIdx.x * 2;
    const int tok1 = tok0 + 1;
    const bool has1 = (tok1 < N);

    const int sid0 = __ldg(sorted_ids + tok0);
    const int e0   = __ldg(topk + tok0);
    int sid1 = sid0, e1 = e0;
    if (has1) { sid1 = __ldg(sorted_ids + tok1); e1 = __ldg(topk + tok1); }

    __shared__ float wmax[2][NTHREADS / 32];

    // ---- token0: loads + act (S0 loaded alongside; it's needed immediately) ----
    const float4* g0 = reinterpret_cast<const float4*>(input + (size_t)sid0 * (size_t)(2 * d));
    const float4* u0 = g0 + (d >> 2);
    const float4* s0 = reinterpret_cast<const float4*>(smooth_scale + (size_t)e0 * (size_t)d);

    float4 A0[D4PER];
    {
        float4 G[D4PER], U[D4PER], S[D4PER];
        #pragma unroll
        for (int k = 0; k < D4PER; k++) {
            const int i = t + k * NTHREADS;
            G[k] = __ldg(g0 + i);
            U[k] = __ldg(u0 + i);
            S[k] = __ldg(s0 + i);
        }
        #pragma unroll
        for (int k = 0; k < D4PER; k++) {
            A0[k].x = silu_fast(G[k].x) * U[k].x * S[k].x;
            A0[k].y = silu_fast(G[k].y) * U[k].y * S[k].y;
            A0[k].z = silu_fast(G[k].z) * U[k].z * S[k].z;
            A0[k].w = silu_fast(G[k].w) * U[k].w * S[k].w;
        }
    }
    float am0 = 0.0f;
    #pragma unroll
    for (int k = 0; k < D4PER; k++) am0 = amax4(am0, A0[k]);

    // ---- token1 DRAM loads issued NOW (in flight during token0 tail) ----
    const float4* g1 = reinterpret_cast<const float4*>(input + (size_t)sid1 * (size_t)(2 * d));
    const float4* u1 = g1 + (d >> 2);
    float4 G1[D4PER], U1[D4PER];
    if (has1) {
        #pragma unroll
        for (int k = 0; k < D4PER; k++) {
            const int i = t + k * NTHREADS;
            G1[k] = __ldg(g1 + i);
            U1[k] = __ldg(u1 + i);
        }
    }

    // ---- token0 reduce + store ----
    {
        float am = am0;
        #pragma unroll
        for (int o = 16; o > 0; o >>= 1)
            am = fmaxf(am, __shfl_xor_sync(0xffffffffu, am, o));
        if ((t & 31) == 0) wmax[0][t >> 5] = am;
    }
    __syncthreads();
    {
        float bmax = wmax[0][0];
        #pragma unroll
        for (int w = 1; w < NTHREADS / 32; w++) bmax = fmaxf(bmax, wmax[0][w]);
        const float scale     = (bmax > 0.0f) ? __fdiv_rn(bmax, 127.0f) : 1.0f;
        const float inv_scale = (bmax > 0.0f) ? __fdividef(127.0f, bmax) : 1.0f;
        if (t == 0) qscale[tok0] = scale;

        if (OUT_FLOAT) {
            float4* orow = reinterpret_cast<float4*>((float*)qout + (size_t)tok0 * (size_t)d);
            #pragma unroll
            for (int k = 0; k < D4PER; k++) {
                const int i = t + k * NTHREADS;
                float4 f;
                f.x = quantf(A0[k].x, inv_scale);
                f.y = quantf(A0[k].y, inv_scale);
                f.z = quantf(A0[k].z, inv_scale);
                f.w = quantf(A0[k].w, inv_scale);
                __stcs(orow + i, f);
            }
        } else {
            char4* orow = reinterpret_cast<char4*>((int8_t*)qout + (size_t)tok0 * (size_t)d);
            #pragma unroll
            for (int k = 0; k < D4PER; k++) {
                const int i = t + k * NTHREADS;
                char4 c;
                c.x = (char)quanti(A0[k].x, inv_scale);
                c.y = (char)quanti(A0[k].y, inv_scale);
                c.z = (char)quanti(A0[k].z, inv_scale);
                c.w = (char)quanti(A0[k].w, inv_scale);
                orow[i] = c;
            }
        }
    }

    if (!has1) return;

    // ---- token1 compute; S1 loaded here (L1-resident table, ~hit latency) ----
    const float4* s1 = reinterpret_cast<const float4*>(smooth_scale + (size_t)e1 * (size_t)d);
    float4 A1[D4PER];
    #pragma unroll
    for (int k = 0; k < D4PER; k++) {
        const int i = t + k * NTHREADS;
        const float4 S = __ldg(s1 + i);
        A1[k].x = silu_fast(G1[k].x) * U1[k].x * S.x;
        A1[k].y = silu_fast(G1[k].y) * U1[k].y * S.y;
        A1[k].z = silu_fast(G1[k].z) * U1[k].z * S.z;
        A1[k].w = silu_fast(G1[k].w) * U1[k].w * S.w;
    }
    float am1 = 0.0f;
    #pragma unroll
    for (int k = 0; k < D4PER; k++) am1 = amax4(am1, A1[k]);

    {
        float am = am1;
        #pragma unroll
        for (int o = 16; o > 0; o >>= 1)
            am = fmaxf(am, __shfl_xor_sync(0xffffffffu, am, o));
        if ((t & 31) == 0) wmax[1][t >> 5] = am;
    }
    __syncthreads();
    {
        float bmax = wmax[1][0];
        #pragma unroll
        for (int w = 1; w < NTHREADS / 32; w++) bmax = fmaxf(bmax, wmax[1][w]);
        const float scale     = (bmax > 0.0f) ? __fdiv_rn(bmax, 127.0f) : 1.0f;
        const float inv_scale = (bmax > 0.0f) ? __fdividef(127.0f, bmax) : 1.0f;
        if (t == 0) qscale[tok1] = scale;

        if (OUT_FLOAT) {
            float4* orow = reinterpret_cast<float4*>((float*)qout + (size_t)tok1 * (size_t)d);
            #pragma unroll
            for (int k = 0; k < D4PER; k++) {
                const int i = t + k * NTHREADS;
                float4 f;
                f.x = quantf(A1[k].x, inv_scale);
                f.y = quantf(A1[k].y, inv_scale);
                f.z = quantf(A1[k].z, inv_scale);
                f.w = quantf(A1[k].w, inv_scale);
                __stcs(orow + i, f);
            }
        } else {
            char4* orow = reinterpret_cast<char4*>((int8_t*)qout + (size_t)tok1 * (size_t)d);
            #pragma unroll
            for (int k = 0; k < D4PER; k++) {
                const int i = t + k * NTHREADS;
                char4 c;
                c.x = (char)quanti(A1[k].x, inv_scale);
                c.y = (char)quanti(A1[k].y, inv_scale);
                c.z = (char)quanti(A1[k].z, inv_scale);
                c.w = (char)quanti(A1[k].w, inv_scale);
                orow[i] = c;
            }
        }
    }
}

// Generic fallback for any d (smem-staged act), one CTA per token.
template <bool OUT_FLOAT>
__global__ __launch_bounds__(256, 1)
void swiglu_quant_generic(const float* __restrict__ input,
                          const float* __restrict__ smooth_scale,
                          const int*   __restrict__ sorted_ids,
                          const int*   __restrict__ topk,
                          void*        __restrict__ qout,
                          float*       __restrict__ qscale,
                          int d)
{
    extern __shared__ float s_act[];
    const int token = blockIdx.x;
    const int t     = threadIdx.x;

    const int sid = __ldg(sorted_ids + token);
    const int e   = __ldg(topk + token);

    const float* gate = input + (size_t)sid * (size_t)(2 * d);
    const float* up   = gate + d;
    const float* ss   = smooth_scale + (size_t)e * (size_t)d;

    float amax = 0.0f;
    for (int j = t; j < d; j += blockDim.x) {
        float a = silu_fast(__ldg(gate + j)) * __ldg(up + j) * __ldg(ss + j);
        s_act[j] = a;
        amax = fmaxf(amax, fabsf(a));
    }

    __shared__ float wmax[8];
    #pragma unroll
    for (int o = 16; o > 0; o >>= 1)
        amax = fmaxf(amax, __shfl_xor_sync(0xffffffffu, amax, o));
    if ((t & 31) == 0) wmax[t >> 5] = amax;
    __syncthreads();
    float bmax = wmax[0];
    #pragma unroll
    for (int w = 1; w < 8; w++) bmax = fmaxf(bmax, wmax[w]);

    const float scale     = (bmax > 0.0f) ? __fdiv_rn(bmax, 127.0f) : 1.0f;
    const float inv_scale = (bmax > 0.0f) ? __fdividef(127.0f, bmax) : 1.0f;
    if (t == 0) qscale[token] = scale;

    if (OUT_FLOAT) {
        float* orow = (float*)qout + (size_t)token * (size_t)d;
        for (int j = t; j < d; j += blockDim.x)
            orow[j] = quantf(s_act[j], inv_scale);
    } else {
        int8_t* orow = (int8_t*)qout + (size_t)token * (size_t)d;
        for (int j = t; j < d; j += blockDim.x)
            orow[j] = (int8_t)quanti(s_act[j], inv_scale);
    }
}

extern "C" void kernel_launch(void* const* d_in, const int* in_sizes, int n_in,
                              void* d_out, int out_size)
{
    const float* input        = (const float*)d_in[0];
    const float* smooth_scale = (const float*)d_in[1];
    const int*   sorted_ids   = (const int*)d_in[2];
    const int*   topk         = (const int*)d_in[3];

    const int N   = in_sizes[2];             // tokens (16384)
    const int fc1 = in_sizes[0] / N;         // 4096
    const int d   = fc1 / 2;                 // 2048

    // Output packing (f32 common dtype confirmed in R3/R4):
    const long long want_f32 = (long long)N * d + N;
    const bool out_float = ((long long)out_size == want_f32);

    void*  qout   = d_out;
    float* qscale = out_float
        ? ((float*)d_out + (size_t)N * (size_t)d)
        : (float*)((int8_t*)d_out + (size_t)N * (size_t)d);

    const int per = d / (4 * NTHREADS);      // float4s per thread per half (2 for d=2048)
    const bool fast = (d % (4 * NTHREADS) == 0) && per >= 1 && per <= 2;
    const int gridPair = (N + 1) / 2;

    if (fast) {
        if (out_float) {
            if (per == 1) swiglu_quant_pair<1, true><<<gridPair, NTHREADS>>>(input, smooth_scale, sorted_ids, topk, qout, qscale, d, N);
            else          swiglu_quant_pair<2, true><<<gridPair, NTHREADS>>>(input, smooth_scale, sorted_ids, topk, qout, qscale, d, N);
        } else {
            if (per == 1) swiglu_quant_pair<1, false><<<gridPair, NTHREADS>>>(input, smooth_scale, sorted_ids, topk, qout, qscale, d, N);
            else          swiglu_quant_pair<2, false><<<gridPair, NTHREADS>>>(input, smooth_scale, sorted_ids, topk, qout, qscale, d, N);
        }
    } else {
        if (out_float)
            swiglu_quant_generic<true><<<N, 256, d * sizeof(float)>>>(input, smooth_scale, sorted_ids, topk, qout, qscale, d);
        else
            swiglu_quant_generic<false><<<N, 256, d * sizeof(float)>>>(input, smooth_scale, sorted_ids, topk, qout, qscale, d);
    }
}